// round 2
// baseline (speedup 1.0000x reference)
#include <cuda_runtime.h>
#include <math.h>

#define B_  32
#define T0_ 2048
#define T1_ 2044
#define T2_ 2040
#define T3_ 2034

// ---------------- scratch (device globals; no allocations allowed) ----------
__device__ float g_xT  [20   * B_ * T0_];
__device__ float g_act1[512  * B_ * T1_];
__device__ float g_act2[512  * B_ * T2_];
__device__ float g_act3[512  * B_ * T3_];
__device__ float g_act4[512  * B_ * T3_];
__device__ float g_act5[1500 * B_ * T3_];
__device__ float g_scl [1500];
__device__ float g_shf [1500];
__device__ float g_pool[B_ * 3000];
__device__ float g_y1  [B_ * 512];
__device__ float g_y2  [B_ * 512];

// ---------------- transpose x[b][t][f] -> xT[f][b][t] -----------------------
__global__ void transpose_x(const float* __restrict__ x, float* __restrict__ xT) {
    int idx = blockIdx.x * blockDim.x + threadIdx.x;
    const int total = B_ * T0_ * 20;
    if (idx >= total) return;
    int f = idx % 20;
    int t = (idx / 20) % T0_;
    int b = idx / (20 * T0_);
    xT[((size_t)f * B_ + b) * T0_ + t] = x[idx];
}

// ---------------- fused splice + 1x1 conv GEMM -------------------------------
// Y[m][b][t] = act( sum_k W[m][k] * X[f(k)][b][t + off(k)] + bias[m] )
//   k = f*C + c,  off = c*offStride.  X layout [F][B][Tin], Y layout [M][B][Tout].
#define TBM 128
#define TBN 128
#define TBK 16

__global__ __launch_bounds__(256)
void gemm_splice(const float* __restrict__ W, const float* __restrict__ bias,
                 const float* __restrict__ X, float* __restrict__ Y,
                 int M, int K, int C, int offStride,
                 int Tin, int Tout, int actMode)
{
    __shared__ float As[TBK][TBM];
    __shared__ float Bs[TBK][TBN];

    const int b     = blockIdx.z;
    const int m0    = blockIdx.y * TBM;
    const int tbase = blockIdx.x * TBN;
    const int tid   = threadIdx.x;
    const int tx    = tid & 15;
    const int ty    = tid >> 4;

    const float* Xb = X + (size_t)b * Tin;

    float acc[8][8];
#pragma unroll
    for (int i = 0; i < 8; i++)
#pragma unroll
        for (int j = 0; j < 8; j++) acc[i][j] = 0.f;

    const int aRow  = tid >> 1;         // 0..127
    const int aCol0 = (tid & 1) * 8;    // 0 or 8
    const int bRow  = tid >> 4;         // 0..15
    const int bCol0 = (tid & 15) * 8;   // 0..120

    for (int k0 = 0; k0 < K; k0 += TBK) {
        // ---- load W tile (zero-padded at K / M edges) ----
        {
            int m = m0 + aRow;
#pragma unroll
            for (int j = 0; j < 8; j++) {
                int k = k0 + aCol0 + j;
                float v = 0.f;
                if (k < K && m < M) v = W[(size_t)m * K + k];
                As[aCol0 + j][aRow] = v;
            }
        }
        // ---- load X tile with splice gather ----
        {
            int k = k0 + bRow;
            bool kv = (k < K);
            int f = 0, off = 0;
            if (kv) { f = k / C; off = (k - f * C) * offStride; }
            const float* src = Xb + (size_t)f * (B_ * (size_t)Tin) + off + tbase + bCol0;
#pragma unroll
            for (int j = 0; j < 8; j++) {
                int t = tbase + bCol0 + j;
                Bs[bRow][bCol0 + j] = (kv && t < Tout) ? src[j] : 0.f;
            }
        }
        __syncthreads();

#pragma unroll
        for (int kk = 0; kk < TBK; kk++) {
            float a[8], bb[8];
            float4 a0 = *(const float4*)&As[kk][ty * 8];
            float4 a1 = *(const float4*)&As[kk][ty * 8 + 4];
            float4 b0 = *(const float4*)&Bs[kk][tx * 8];
            float4 b1 = *(const float4*)&Bs[kk][tx * 8 + 4];
            a[0]=a0.x; a[1]=a0.y; a[2]=a0.z; a[3]=a0.w;
            a[4]=a1.x; a[5]=a1.y; a[6]=a1.z; a[7]=a1.w;
            bb[0]=b0.x; bb[1]=b0.y; bb[2]=b0.z; bb[3]=b0.w;
            bb[4]=b1.x; bb[5]=b1.y; bb[6]=b1.z; bb[7]=b1.w;
#pragma unroll
            for (int i = 0; i < 8; i++)
#pragma unroll
                for (int j = 0; j < 8; j++)
                    acc[i][j] += a[i] * bb[j];
        }
        __syncthreads();
    }

    const size_t strideY = (size_t)B_ * Tout;
#pragma unroll
    for (int i = 0; i < 8; i++) {
        int m = m0 + ty * 8 + i;
        if (m >= M) continue;
        float bi = bias[m];
#pragma unroll
        for (int j = 0; j < 8; j++) {
            int t = tbase + tx * 8 + j;
            if (t < Tout) {
                float v = acc[i][j] + bi;
                v = fmaxf(v, 0.f);
                if (actMode) v = fminf(v, 6.f);
                Y[(size_t)m * strideY + (size_t)b * Tout + t] = v;
            }
        }
    }
}

// ---------------- per-channel batch-norm stats (over B*T) -------------------
__global__ void channel_stats(const float* __restrict__ Y, int N,
                              const float* __restrict__ gam, const float* __restrict__ bet,
                              float* __restrict__ scl, float* __restrict__ shf)
{
    int c = blockIdx.x;
    const float4* p = (const float4*)(Y + (size_t)c * N);
    int n4 = N >> 2;
    float s1 = 0.f, s2 = 0.f;
    for (int i = threadIdx.x; i < n4; i += blockDim.x) {
        float4 v = p[i];
        s1 += v.x + v.y + v.z + v.w;
        s2 += v.x*v.x + v.y*v.y + v.z*v.z + v.w*v.w;
    }
    __shared__ float r1[256], r2[256];
    r1[threadIdx.x] = s1; r2[threadIdx.x] = s2;
    __syncthreads();
    for (int s = 128; s > 0; s >>= 1) {
        if (threadIdx.x < s) {
            r1[threadIdx.x] += r1[threadIdx.x + s];
            r2[threadIdx.x] += r2[threadIdx.x + s];
        }
        __syncthreads();
    }
    if (threadIdx.x == 0) {
        float m   = r1[0] / (float)N;
        float var = r2[0] / (float)N - m * m;
        float inv = rsqrtf(var + 1e-5f);
        float g   = gam ? gam[c] : 1.f;
        float be  = bet ? bet[c] : 0.f;
        float A   = g * inv;
        scl[c] = A;
        shf[c] = be - m * A;
    }
}

// ---------------- in-place per-channel affine normalize ---------------------
__global__ void normalize_ip(float* __restrict__ Y, const float* __restrict__ scl,
                             const float* __restrict__ shf, int N)
{
    int c = blockIdx.y;
    float a = scl[c], d = shf[c];
    float4* p = (float4*)(Y + (size_t)c * N);
    int n4 = N >> 2;
    for (int i = blockIdx.x * blockDim.x + threadIdx.x; i < n4; i += gridDim.x * blockDim.x) {
        float4 v = p[i];
        v.x = a * v.x + d; v.y = a * v.y + d;
        v.z = a * v.z + d; v.w = a * v.w + d;
        p[i] = v;
    }
}

// ---------------- stats pooling: mean + unbiased std over time --------------
__global__ void pool_stats(const float* __restrict__ A, float* __restrict__ P)
{
    int c = blockIdx.x;  // 0..1499
    int b = blockIdx.y;  // 0..31
    const float* p = A + ((size_t)c * B_ + b) * T3_;
    float s1 = 0.f, s2 = 0.f;
    for (int i = threadIdx.x; i < T3_; i += blockDim.x) {
        float v = p[i]; s1 += v; s2 += v * v;
    }
    __shared__ float r1[128], r2[128];
    r1[threadIdx.x] = s1; r2[threadIdx.x] = s2;
    __syncthreads();
    for (int s = 64; s > 0; s >>= 1) {
        if (threadIdx.x < s) {
            r1[threadIdx.x] += r1[threadIdx.x + s];
            r2[threadIdx.x] += r2[threadIdx.x + s];
        }
        __syncthreads();
    }
    if (threadIdx.x == 0) {
        float m   = r1[0] / (float)T3_;
        float var = (r2[0] - (float)T3_ * m * m) / (float)(T3_ - 1);
        P[b * 3000 + c]        = m;
        P[b * 3000 + 1500 + c] = sqrtf(fmaxf(var, 0.f));
    }
}

// ---------------- dense + relu6 (one warp per output) -----------------------
__global__ void dense_relu6(const float* __restrict__ W, const float* __restrict__ bias,
                            const float* __restrict__ X, float* __restrict__ Y,
                            int M, int K)
{
    int gw   = (blockIdx.x * blockDim.x + threadIdx.x) >> 5;
    int lane = threadIdx.x & 31;
    if (gw >= B_ * M) return;
    int b = gw / M, o = gw - b * M;
    const float* w = W + (size_t)o * K;
    const float* x = X + (size_t)b * K;
    float s = 0.f;
    for (int k = lane; k < K; k += 32) s += w[k] * x[k];
#pragma unroll
    for (int off = 16; off; off >>= 1) s += __shfl_xor_sync(0xffffffffu, s, off);
    if (lane == 0) {
        float v = s + bias[o];
        Y[(size_t)b * M + o] = fminf(fmaxf(v, 0.f), 6.f);
    }
}

// ---------------- batch-norm over batch dim (B=32 == warp) ------------------
__global__ void bn_batch(const float* __restrict__ Y, const float* __restrict__ gam,
                         const float* __restrict__ bet, float* __restrict__ Out, int M)
{
    int o    = (blockIdx.x * blockDim.x + threadIdx.x) >> 5;
    int lane = threadIdx.x & 31;
    if (o >= M) return;
    float v  = Y[(size_t)lane * M + o];
    float s1 = v, s2 = v * v;
#pragma unroll
    for (int off = 16; off; off >>= 1) {
        s1 += __shfl_xor_sync(0xffffffffu, s1, off);
        s2 += __shfl_xor_sync(0xffffffffu, s2, off);
    }
    float m   = s1 * (1.f / 32.f);
    float var = s2 * (1.f / 32.f) - m * m;
    float r   = rsqrtf(var + 1e-5f);
    Out[(size_t)lane * M + o] = (v - m) * r * gam[o] + bet[o];
}

// ---------------- launch ----------------------------------------------------
extern "C" void kernel_launch(void* const* d_in, const int* in_sizes, int n_in,
                              void* d_out, int out_size)
{
    const float* x     = (const float*)d_in[0];
    const float* h1_w  = (const float*)d_in[1];
    const float* h1_b  = (const float*)d_in[2];
    const float* h2_w  = (const float*)d_in[3];
    const float* h2_b  = (const float*)d_in[4];
    const float* bn2_g = (const float*)d_in[5];
    const float* bn2_b = (const float*)d_in[6];
    const float* h3_w  = (const float*)d_in[7];
    const float* h3_b  = (const float*)d_in[8];
    const float* bn3_g = (const float*)d_in[9];
    const float* bn3_b = (const float*)d_in[10];
    const float* h4_w  = (const float*)d_in[11];
    const float* h4_b  = (const float*)d_in[12];
    const float* bn4_g = (const float*)d_in[13];
    const float* bn4_b = (const float*)d_in[14];
    const float* h5_w  = (const float*)d_in[15];
    const float* h5_b  = (const float*)d_in[16];
    const float* bn5_g = (const float*)d_in[17];
    const float* bn5_b = (const float*)d_in[18];
    const float* l1_w  = (const float*)d_in[19];
    const float* l1_b  = (const float*)d_in[20];
    const float* bn6_g = (const float*)d_in[21];
    const float* bn6_b = (const float*)d_in[22];
    const float* l2_w  = (const float*)d_in[23];
    const float* l2_b  = (const float*)d_in[24];
    const float* bn7_g = (const float*)d_in[25];
    const float* bn7_b = (const float*)d_in[26];

    float *xT, *a1, *a2, *a3, *a4, *a5, *scl, *shf, *pool, *y1, *y2;
    cudaGetSymbolAddress((void**)&xT,   g_xT);
    cudaGetSymbolAddress((void**)&a1,   g_act1);
    cudaGetSymbolAddress((void**)&a2,   g_act2);
    cudaGetSymbolAddress((void**)&a3,   g_act3);
    cudaGetSymbolAddress((void**)&a4,   g_act4);
    cudaGetSymbolAddress((void**)&a5,   g_act5);
    cudaGetSymbolAddress((void**)&scl,  g_scl);
    cudaGetSymbolAddress((void**)&shf,  g_shf);
    cudaGetSymbolAddress((void**)&pool, g_pool);
    cudaGetSymbolAddress((void**)&y1,   g_y1);
    cudaGetSymbolAddress((void**)&y2,   g_y2);

    const int N1 = B_ * T1_;   // 65408
    const int N2 = B_ * T2_;   // 65280
    const int N3 = B_ * T3_;   // 65088

    transpose_x<<<(B_ * T0_ * 20 + 255) / 256, 256>>>(x, xT);

    // Layer 1: splice(0..4) + h1 + relu + bn (no affine)
    gemm_splice<<<dim3((T1_ + 127) / 128, 4, B_), 256>>>(
        h1_w, h1_b, xT, a1, 512, 100, 5, 1, T0_, T1_, 0);
    channel_stats<<<512, 256>>>(a1, N1, nullptr, nullptr, scl, shf);
    normalize_ip<<<dim3(32, 512), 256>>>(a1, scl, shf, N1);

    // Layer 2: splice(0,2,4) + h2 + relu + bn2
    gemm_splice<<<dim3((T2_ + 127) / 128, 4, B_), 256>>>(
        h2_w, h2_b, a1, a2, 512, 1536, 3, 2, T1_, T2_, 0);
    channel_stats<<<512, 256>>>(a2, N2, bn2_g, bn2_b, scl, shf);
    normalize_ip<<<dim3(32, 512), 256>>>(a2, scl, shf, N2);

    // Layer 3: splice(0,3,6) + h3 + relu + bn3
    gemm_splice<<<dim3((T3_ + 127) / 128, 4, B_), 256>>>(
        h3_w, h3_b, a2, a3, 512, 1536, 3, 3, T2_, T3_, 0);
    channel_stats<<<512, 256>>>(a3, N3, bn3_g, bn3_b, scl, shf);
    normalize_ip<<<dim3(32, 512), 256>>>(a3, scl, shf, N3);

    // Layer 4: h4 + relu6 + bn4
    gemm_splice<<<dim3((T3_ + 127) / 128, 4, B_), 256>>>(
        h4_w, h4_b, a3, a4, 512, 512, 1, 0, T3_, T3_, 1);
    channel_stats<<<512, 256>>>(a4, N3, bn4_g, bn4_b, scl, shf);
    normalize_ip<<<dim3(32, 512), 256>>>(a4, scl, shf, N3);

    // Layer 5: h5 + relu6 + bn5
    gemm_splice<<<dim3((T3_ + 127) / 128, 12, B_), 256>>>(
        h5_w, h5_b, a4, a5, 1500, 512, 1, 0, T3_, T3_, 1);
    channel_stats<<<1500, 256>>>(a5, N3, bn5_g, bn5_b, scl, shf);
    normalize_ip<<<dim3(32, 1500), 256>>>(a5, scl, shf, N3);

    // Stats pooling -> [B, 3000]
    pool_stats<<<dim3(1500, B_), 128>>>(a5, pool);

    // l1 + relu6 + bn6 (over batch)
    dense_relu6<<<(B_ * 512 * 32 + 255) / 256, 256>>>(l1_w, l1_b, pool, y1, 512, 3000);
    bn_batch<<<(512 * 32 + 255) / 256, 256>>>(y1, bn6_g, bn6_b, y1, 512);

    // l2 + relu6 + bn7 -> output [32, 512]
    dense_relu6<<<(B_ * 512 * 32 + 255) / 256, 256>>>(l2_w, l2_b, y1, y2, 512, 512);
    bn_batch<<<(512 * 32 + 255) / 256, 256>>>(y2, bn7_g, bn7_b, (float*)d_out, 512);
}